// round 4
// baseline (speedup 1.0000x reference)
#include <cuda_runtime.h>

#define LQ 4096
#define SK 4096
#define NH_TOT 64      // N*H = 8*8
#define DD 64
#define MM 64
#define S1_CHUNKS 16
#define LT2 128

typedef unsigned long long ull;

// Scratch (__device__ globals; no allocation allowed)
__device__ float g_KVp[S1_CHUNKS * NH_TOT * DD * MM];   // per-chunk partial KV
__device__ float g_Ksp[S1_CHUNKS * NH_TOT * DD];        // per-chunk partial Ksum
__device__ float g_KV [NH_TOT * DD * MM];
__device__ float g_Ksum[NH_TOT * DD];

__device__ __forceinline__ float phi(float x) {         // elu(x)+1
    return x > 0.f ? x + 1.f : __expf(x);
}
__device__ __forceinline__ ull pack2(float lo, float hi) {
    ull r; asm("mov.b64 %0, {%1, %2};" : "=l"(r) : "f"(lo), "f"(hi)); return r;
}
__device__ __forceinline__ void ffma2(ull &d, ull a, ull b) {
    asm("fma.rn.f32x2 %0, %1, %2, %0;" : "+l"(d) : "l"(a), "l"(b));
}
__device__ __forceinline__ ull mul2(ull a, ull b) {
    ull d; asm("mul.rn.f32x2 %0, %1, %2;" : "=l"(d) : "l"(a), "l"(b)); return d;
}

union F4U { float4 f; ull u[2]; float s[4]; };

// ───────────────────────── Stage 1 ─────────────────────────
// Each block: one nh, 512 s-rows. Two half-blocks (64 threads) each own an
// independent s-partition (chunk) and a full 64x64 accumulator; per-thread
// tile is 8d x 8m. Shared tile: 32 s-rows of K (phi+mask applied) and V.
__global__ __launch_bounds__(128) void stage1_kernel(
    const float* __restrict__ Kg, const float* __restrict__ Vg,
    const float* __restrict__ maskg)
{
    const int nh = blockIdx.x, sc = blockIdx.y;       // sc: 0..7
    const int n = nh >> 3, h = nh & 7;
    const int tid = threadIdx.x;
    const int half = tid >> 6;
    const int tt = tid & 63;
    const int trow = tt >> 3;     // d tile: 8*trow..+7
    const int tcol = tt & 7;      // m tile: 8*tcol..+7

    __shared__ __align__(16) float ks[32][DD];
    __shared__ __align__(16) float vs[32][MM];

    ull acc[8][4];
    #pragma unroll
    for (int i = 0; i < 8; i++)
        #pragma unroll
        for (int j = 0; j < 4; j++) acc[i][j] = 0ull;
    float ksum[8] = {0.f, 0.f, 0.f, 0.f, 0.f, 0.f, 0.f, 0.f};

    const int s0 = sc * 512;

    for (int b = 0; b < 512; b += 32) {
        // Produce 32-row K/V tiles (each thread: 4 K-float4 + 4 V-float4)
        #pragma unroll
        for (int u = 0; u < 4; u++) {
            const int li = tid + 128 * u;     // 0..511
            const int r = li >> 4, c = li & 15;
            const int s = s0 + b + r;
            const int base = ((n * SK + s) * 8 + h) * DD;
            F4U k4; k4.f = *((const float4*)(Kg + base) + c);
            const float mk = maskg[n * SK + s];
            k4.s[0] = phi(k4.s[0]) * mk; k4.s[1] = phi(k4.s[1]) * mk;
            k4.s[2] = phi(k4.s[2]) * mk; k4.s[3] = phi(k4.s[3]) * mk;
            ((float4*)&ks[r][0])[c] = k4.f;
            F4U v4; v4.f = *((const float4*)(Vg + base) + c);
            ((float4*)&vs[r][0])[c] = v4.f;
        }
        __syncthreads();
        #pragma unroll
        for (int r = 0; r < 16; r++) {
            const int row = (half << 4) + r;
            F4U ka, kb, va, vb;
            ka.f = ((const float4*)&ks[row][0])[2 * trow];
            kb.f = ((const float4*)&ks[row][0])[2 * trow + 1];
            va.f = ((const float4*)&vs[row][0])[2 * tcol];
            vb.f = ((const float4*)&vs[row][0])[2 * tcol + 1];
            #pragma unroll
            for (int i = 0; i < 4; i++) {
                const ull kd = pack2(ka.s[i], ka.s[i]);
                ffma2(acc[i][0], kd, va.u[0]);
                ffma2(acc[i][1], kd, va.u[1]);
                ffma2(acc[i][2], kd, vb.u[0]);
                ffma2(acc[i][3], kd, vb.u[1]);
            }
            #pragma unroll
            for (int i = 0; i < 4; i++) {
                const ull kd = pack2(kb.s[i], kb.s[i]);
                ffma2(acc[4 + i][0], kd, va.u[0]);
                ffma2(acc[4 + i][1], kd, va.u[1]);
                ffma2(acc[4 + i][2], kd, vb.u[0]);
                ffma2(acc[4 + i][3], kd, vb.u[1]);
            }
            if (tcol == 0) {
                #pragma unroll
                for (int i = 0; i < 4; i++) {
                    ksum[i]     += ka.s[i];
                    ksum[4 + i] += kb.s[i];
                }
            }
        }
        __syncthreads();
    }

    const int chunk = 2 * sc + half;
    float* dst = g_KVp + ((chunk * NH_TOT + nh) * DD + 8 * trow) * MM + 8 * tcol;
    #pragma unroll
    for (int i = 0; i < 8; i++) {
        F4U lo, hi;
        lo.u[0] = acc[i][0]; lo.u[1] = acc[i][1];
        hi.u[0] = acc[i][2]; hi.u[1] = acc[i][3];
        *(float4*)(dst + i * MM)     = lo.f;
        *(float4*)(dst + i * MM + 4) = hi.f;
    }
    if (tcol == 0) {
        float* kd = g_Ksp + (chunk * NH_TOT + nh) * DD + 8 * trow;
        #pragma unroll
        for (int i = 0; i < 8; i++) kd[i] = ksum[i];
    }
}

// ───────────────────────── Reduce partials ─────────────────────────
__global__ __launch_bounds__(256) void reduce_kernel() {
    const int idx = blockIdx.x * 256 + threadIdx.x;
    const int KV4 = NH_TOT * DD * MM / 4;    // 65536
    const int KS4 = NH_TOT * DD / 4;         // 1024
    if (idx < KV4) {
        float4 s = make_float4(0.f, 0.f, 0.f, 0.f);
        #pragma unroll
        for (int c = 0; c < S1_CHUNKS; c++) {
            float4 p = ((const float4*)g_KVp)[c * KV4 + idx];
            s.x += p.x; s.y += p.y; s.z += p.z; s.w += p.w;
        }
        ((float4*)g_KV)[idx] = s;
    } else if (idx < KV4 + KS4) {
        const int j = idx - KV4;
        float4 s = make_float4(0.f, 0.f, 0.f, 0.f);
        #pragma unroll
        for (int c = 0; c < S1_CHUNKS; c++) {
            float4 p = ((const float4*)g_Ksp)[c * KS4 + j];
            s.x += p.x; s.y += p.y; s.z += p.z; s.w += p.w;
        }
        ((float4*)g_Ksum)[j] = s;
    }
}

// ───────────────────────── Stage 2 ─────────────────────────
// 128l x 64m per block, 128 threads, per-thread tile 8l x 8m.
// Q transposed in smem [d][l] (stride 132); KV streamed in two 32-d halves.
__global__ __launch_bounds__(128) void stage2_kernel(
    const float* __restrict__ Qg, float* __restrict__ Outg)
{
    const int nh = blockIdx.y;
    const int n = nh >> 3, h = nh & 7;
    const int l0 = blockIdx.x * LT2;
    const int tid = threadIdx.x;
    const int trow = tid >> 3;    // 0..15: l tile 8*trow..+7
    const int tcol = tid & 7;     // 0..7 : m tile 8*tcol..+7

    __shared__ __align__(16) float Qs[DD][132];   // [d][l]
    __shared__ __align__(16) float KVs[32][MM];
    __shared__ float ksums[DD];
    __shared__ float zs[LT2];

    // Load+transpose Q tile with phi applied (coalesced global reads)
    #pragma unroll 4
    for (int u = 0; u < 64; u++) {
        const int idx = tid + 128 * u;      // 0..8191
        const int l = idx >> 6, d = idx & 63;
        Qs[d][l] = phi(Qg[((n * LQ + l0 + l) * 8 + h) * DD + d]);
    }
    if (tid < DD) ksums[tid] = g_Ksum[nh * DD + tid];
    __syncthreads();

    // z[l] = 1/(phi(q)[l] . Ksum + eps)
    {
        float a = 0.f;
        #pragma unroll
        for (int d = 0; d < DD; d++) a = fmaf(Qs[d][tid], ksums[d], a);
        zs[tid] = 1.f / (a + 1e-6f);
    }

    ull acc[8][4];
    #pragma unroll
    for (int i = 0; i < 8; i++)
        #pragma unroll
        for (int j = 0; j < 4; j++) acc[i][j] = 0ull;

    #pragma unroll
    for (int half = 0; half < 2; half++) {
        __syncthreads();
        // Load this 32-d half of KV (L2-resident; 512 float4)
        #pragma unroll
        for (int u = 0; u < 4; u++) {
            const int i4 = tid + 128 * u;            // 0..511
            ((float4*)KVs)[i4] =
                ((const float4*)(g_KV + (nh * DD + 32 * half) * MM))[i4];
        }
        __syncthreads();

        #pragma unroll 4
        for (int dp = 0; dp < 32; dp++) {
            const int d = 32 * half + dp;
            F4U qa, qb, ka, kb;
            qa.f = ((const float4*)&Qs[d][0])[2 * trow];
            qb.f = ((const float4*)&Qs[d][0])[2 * trow + 1];
            ka.f = ((const float4*)&KVs[dp][0])[2 * tcol];
            kb.f = ((const float4*)&KVs[dp][0])[2 * tcol + 1];
            #pragma unroll
            for (int i = 0; i < 4; i++) {
                const ull qq = pack2(qa.s[i], qa.s[i]);
                ffma2(acc[i][0], qq, ka.u[0]);
                ffma2(acc[i][1], qq, ka.u[1]);
                ffma2(acc[i][2], qq, kb.u[0]);
                ffma2(acc[i][3], qq, kb.u[1]);
            }
            #pragma unroll
            for (int i = 0; i < 4; i++) {
                const ull qq = pack2(qb.s[i], qb.s[i]);
                ffma2(acc[4 + i][0], qq, ka.u[0]);
                ffma2(acc[4 + i][1], qq, ka.u[1]);
                ffma2(acc[4 + i][2], qq, kb.u[0]);
                ffma2(acc[4 + i][3], qq, kb.u[1]);
            }
        }
    }

    #pragma unroll
    for (int i = 0; i < 8; i++) {
        const int ll = 8 * trow + i;
        const int l = l0 + ll;
        const float z = zs[ll];
        const ull zz = pack2(z, z);
        F4U lo, hi;
        lo.u[0] = mul2(acc[i][0], zz); lo.u[1] = mul2(acc[i][1], zz);
        hi.u[0] = mul2(acc[i][2], zz); hi.u[1] = mul2(acc[i][3], zz);
        float* o = Outg + ((n * LQ + l) * 8 + h) * MM + 8 * tcol;
        *(float4*)o       = lo.f;
        *(float4*)(o + 4) = hi.f;
    }
}

extern "C" void kernel_launch(void* const* d_in, const int* in_sizes, int n_in,
                              void* d_out, int out_size)
{
    const float* Q    = (const float*)d_in[0];
    const float* K    = (const float*)d_in[1];
    const float* V    = (const float*)d_in[2];
    const float* mask = (const float*)d_in[3];
    float* Out = (float*)d_out;

    stage1_kernel<<<dim3(NH_TOT, 8), 128>>>(K, V, mask);
    reduce_kernel<<<260, 256>>>();
    stage2_kernel<<<dim3(LQ / LT2, NH_TOT), 128>>>(Q, Out);
}

// round 6
// speedup vs baseline: 1.7310x; 1.7310x over previous
#include <cuda_runtime.h>

#define LQ 4096
#define SK 4096
#define NH_TOT 64      // N*H = 8*8
#define DD 64
#define MM 64
#define S1_CHUNKS 32
#define S1_ROWS (SK / S1_CHUNKS)   // 128
#define LTILE 64

typedef unsigned long long ull;

// Scratch (__device__ globals; no allocation allowed)
__device__ float g_KVp[S1_CHUNKS * NH_TOT * DD * MM];   // per-chunk partial KV
__device__ float g_Ksp[S1_CHUNKS * NH_TOT * DD];        // per-chunk partial Ksum
__device__ float g_KV [NH_TOT * DD * MM];
__device__ float g_Ksum[NH_TOT * DD];

__device__ __forceinline__ float phi(float x) {         // elu(x)+1
    return x > 0.f ? x + 1.f : __expf(x);
}
__device__ __forceinline__ ull pack2(float lo, float hi) {
    ull r; asm("mov.b64 %0, {%1, %2};" : "=l"(r) : "f"(lo), "f"(hi)); return r;
}
__device__ __forceinline__ void ffma2(ull &d, ull a, ull b) {
    asm("fma.rn.f32x2 %0, %1, %2, %0;" : "+l"(d) : "l"(a), "l"(b));
}
__device__ __forceinline__ ull mul2(ull a, ull b) {
    ull d; asm("mul.rn.f32x2 %0, %1, %2;" : "=l"(d) : "l"(a), "l"(b)); return d;
}

union F4U { float4 f; ull u[2]; float s[4]; };

// ───────────────────────── Stage 1 ─────────────────────────
// grid (64 nh, 32 chunks), 256 threads, per-thread tile 4d x 4m.
// 16-row K/V batches with register-prefetch double buffering.
__global__ __launch_bounds__(256) void stage1_kernel(
    const float* __restrict__ Kg, const float* __restrict__ Vg,
    const float* __restrict__ maskg)
{
    const int nh = blockIdx.x, sc = blockIdx.y;
    const int n = nh >> 3, h = nh & 7;
    const int tid = threadIdx.x;
    const int td = tid >> 4;      // d tile: 4*td..+3
    const int tm = tid & 15;      // m tile: 4*tm..+3

    __shared__ __align__(16) float ks[16][DD];
    __shared__ __align__(16) float vs[16][MM];

    ull acc[4][2];
    #pragma unroll
    for (int i = 0; i < 4; i++) { acc[i][0] = 0ull; acc[i][1] = 0ull; }
    float ksum[4] = {0.f, 0.f, 0.f, 0.f};

    const int s0 = sc * S1_ROWS;
    const int lr = tid >> 4, lc = tid & 15;   // loader: row 0..15, float4 col 0..15

    // Prefetch batch 0 into registers
    F4U kreg, vreg; float mreg;
    {
        const int s = s0 + lr;
        const int base = ((n * SK + s) * 8 + h) * DD;
        kreg.f = *((const float4*)(Kg + base) + lc);
        vreg.f = *((const float4*)(Vg + base) + lc);
        mreg = maskg[n * SK + s];
    }

    #pragma unroll 1
    for (int b = 0; b < S1_ROWS / 16; b++) {
        if (b) __syncthreads();   // prior compute done before overwriting tiles
        // Store current regs (phi+mask applied to K)
        F4U kw = kreg;
        kw.s[0] = phi(kw.s[0]) * mreg; kw.s[1] = phi(kw.s[1]) * mreg;
        kw.s[2] = phi(kw.s[2]) * mreg; kw.s[3] = phi(kw.s[3]) * mreg;
        ((float4*)&ks[lr][0])[lc] = kw.f;
        ((float4*)&vs[lr][0])[lc] = vreg.f;
        __syncthreads();
        // Prefetch next batch while computing
        if (b + 1 < S1_ROWS / 16) {
            const int s = s0 + (b + 1) * 16 + lr;
            const int base = ((n * SK + s) * 8 + h) * DD;
            kreg.f = *((const float4*)(Kg + base) + lc);
            vreg.f = *((const float4*)(Vg + base) + lc);
            mreg = maskg[n * SK + s];
        }
        #pragma unroll
        for (int r = 0; r < 16; r++) {
            F4U k4, v4;
            k4.f = ((const float4*)&ks[r][0])[td];
            v4.f = ((const float4*)&vs[r][0])[tm];
            #pragma unroll
            for (int i = 0; i < 4; i++) {
                const ull kd = pack2(k4.s[i], k4.s[i]);
                ffma2(acc[i][0], kd, v4.u[0]);
                ffma2(acc[i][1], kd, v4.u[1]);
            }
            if (tm == 0) {
                #pragma unroll
                for (int i = 0; i < 4; i++) ksum[i] += k4.s[i];
            }
        }
    }

    float* dst = g_KVp + ((sc * NH_TOT + nh) * DD + 4 * td) * MM + 4 * tm;
    #pragma unroll
    for (int i = 0; i < 4; i++) {
        F4U o; o.u[0] = acc[i][0]; o.u[1] = acc[i][1];
        *(float4*)(dst + i * MM) = o.f;
    }
    if (tm == 0) {
        float* kd = g_Ksp + (sc * NH_TOT + nh) * DD + 4 * td;
        #pragma unroll
        for (int i = 0; i < 4; i++) kd[i] = ksum[i];
    }
}

// ───────────────────────── Reduce partials ─────────────────────────
__global__ __launch_bounds__(256) void reduce_kernel() {
    const int idx = blockIdx.x * 256 + threadIdx.x;
    const int KV4 = NH_TOT * DD * MM / 4;    // 65536
    const int KS4 = NH_TOT * DD / 4;         // 1024
    if (idx < KV4) {
        float4 s = make_float4(0.f, 0.f, 0.f, 0.f);
        #pragma unroll 8
        for (int c = 0; c < S1_CHUNKS; c++) {
            float4 p = ((const float4*)g_KVp)[c * KV4 + idx];
            s.x += p.x; s.y += p.y; s.z += p.z; s.w += p.w;
        }
        ((float4*)g_KV)[idx] = s;
    } else if (idx < KV4 + KS4) {
        const int j = idx - KV4;
        float4 s = make_float4(0.f, 0.f, 0.f, 0.f);
        #pragma unroll 8
        for (int c = 0; c < S1_CHUNKS; c++) {
            float4 p = ((const float4*)g_Ksp)[c * KS4 + j];
            s.x += p.x; s.y += p.y; s.z += p.z; s.w += p.w;
        }
        ((float4*)g_Ksum)[j] = s;
    }
}

// ───────────────────────── Stage 2 ─────────────────────────
// grid (64 l-tiles, 64 nh), 256 threads, per-thread tile 4l x 4m.
__global__ __launch_bounds__(256) void stage2_kernel(
    const float* __restrict__ Qg, float* __restrict__ Outg)
{
    const int nh = blockIdx.y;
    const int n = nh >> 3, h = nh & 7;
    const int l0 = blockIdx.x * LTILE;
    const int tid = threadIdx.x;
    const int tl = tid >> 4;      // l tile: 4*tl..+3
    const int tm = tid & 15;      // m tile: 4*tm..+3

    __shared__ __align__(16) float Qs[DD][68];    // [d][l], transposed
    __shared__ __align__(16) float KVs[DD][MM];
    __shared__ float ksums[DD];
    __shared__ float zs[LTILE];

    // Load+transpose Q tile with phi applied (coalesced scalar reads)
    #pragma unroll 4
    for (int u = 0; u < 16; u++) {
        const int idx = tid + 256 * u;       // 0..4095
        const int l = idx >> 6, d = idx & 63;
        Qs[d][l] = phi(Qg[((n * LQ + l0 + l) * 8 + h) * DD + d]);
    }
    // Load KV (L2-resident) and Ksum
    #pragma unroll
    for (int u = 0; u < 4; u++)
        ((float4*)KVs)[tid + 256 * u] = ((const float4*)(g_KV + nh * DD * MM))[tid + 256 * u];
    if (tid < DD) ksums[tid] = g_Ksum[nh * DD + tid];
    __syncthreads();

    // z[l] = 1/(phi(q)[l] . Ksum + eps)
    if (tid < LTILE) {
        float a = 0.f;
        #pragma unroll
        for (int d = 0; d < DD; d++) a = fmaf(Qs[d][tid], ksums[d], a);
        zs[tid] = 1.f / (a + 1e-6f);
    }
    __syncthreads();

    ull acc[4][2];
    #pragma unroll
    for (int i = 0; i < 4; i++) { acc[i][0] = 0ull; acc[i][1] = 0ull; }

    #pragma unroll 8
    for (int d = 0; d < DD; d++) {
        F4U q4, k4;
        q4.f = *(const float4*)&Qs[d][4 * tl];
        k4.f = ((const float4*)&KVs[d][0])[tm];
        #pragma unroll
        for (int i = 0; i < 4; i++) {
            const ull qq = pack2(q4.s[i], q4.s[i]);
            ffma2(acc[i][0], qq, k4.u[0]);
            ffma2(acc[i][1], qq, k4.u[1]);
        }
    }

    #pragma unroll
    for (int i = 0; i < 4; i++) {
        const int l = l0 + 4 * tl + i;
        const float z = zs[4 * tl + i];
        const ull zz = pack2(z, z);
        F4U o;
        o.u[0] = mul2(acc[i][0], zz);
        o.u[1] = mul2(acc[i][1], zz);
        *(float4*)(Outg + ((n * LQ + l) * 8 + h) * MM + 4 * tm) = o.f;
    }
}

extern "C" void kernel_launch(void* const* d_in, const int* in_sizes, int n_in,
                              void* d_out, int out_size)
{
    const float* Q    = (const float*)d_in[0];
    const float* K    = (const float*)d_in[1];
    const float* V    = (const float*)d_in[2];
    const float* mask = (const float*)d_in[3];
    float* Out = (float*)d_out;

    stage1_kernel<<<dim3(NH_TOT, S1_CHUNKS), 256>>>(K, V, mask);
    reduce_kernel<<<260, 256>>>();
    stage2_kernel<<<dim3(LQ / LTILE, NH_TOT), 256>>>(Q, Out);
}

// round 7
// speedup vs baseline: 1.8428x; 1.0646x over previous
#include <cuda_runtime.h>

#define LQ 4096
#define SK 4096
#define NH_TOT 64      // N*H = 8*8
#define DD 64
#define MM 64
#define S1_CHUNKS 32
#define S1_ROWS (SK / S1_CHUNKS)   // 128
#define LTILE 64

typedef unsigned long long ull;

// Scratch (__device__ globals; no allocation allowed)
__device__ float g_KVp[S1_CHUNKS * NH_TOT * DD * MM];   // per-chunk partial KV
__device__ float g_Ksp[S1_CHUNKS * NH_TOT * DD];        // per-chunk partial Ksum
__device__ float g_KV [NH_TOT * DD * MM];
__device__ float g_Ksum[NH_TOT * DD];

__device__ __forceinline__ float phi(float x) {         // elu(x)+1
    return x > 0.f ? x + 1.f : __expf(x);
}
__device__ __forceinline__ ull pack2(float lo, float hi) {
    ull r; asm("mov.b64 %0, {%1, %2};" : "=l"(r) : "f"(lo), "f"(hi)); return r;
}
__device__ __forceinline__ void ffma2(ull &d, ull a, ull b) {
    asm("fma.rn.f32x2 %0, %1, %2, %0;" : "+l"(d) : "l"(a), "l"(b));
}
__device__ __forceinline__ ull mul2(ull a, ull b) {
    ull d; asm("mul.rn.f32x2 %0, %1, %2;" : "=l"(d) : "l"(a), "l"(b)); return d;
}

union F4U { float4 f; ull u[2]; float s[4]; };

// ───────────────────────── Stage 1 ─────────────────────────
// grid (64 nh, 32 chunks), 256 threads, per-thread tile 4d x 4m.
// 16-row K/V batches with register-prefetch double buffering.
// launch_bounds(256,4): cap regs at 64 -> 4 resident blocks/SM.
__global__ __launch_bounds__(256, 4) void stage1_kernel(
    const float* __restrict__ Kg, const float* __restrict__ Vg,
    const float* __restrict__ maskg)
{
    const int nh = blockIdx.x, sc = blockIdx.y;
    const int n = nh >> 3, h = nh & 7;
    const int tid = threadIdx.x;
    const int td = tid >> 4;      // d tile: 4*td..+3
    const int tm = tid & 15;      // m tile: 4*tm..+3

    __shared__ __align__(16) float ks[16][DD];
    __shared__ __align__(16) float vs[16][MM];

    ull acc[4][2];
    #pragma unroll
    for (int i = 0; i < 4; i++) { acc[i][0] = 0ull; acc[i][1] = 0ull; }
    float ksum[4] = {0.f, 0.f, 0.f, 0.f};

    const int s0 = sc * S1_ROWS;
    const int lr = tid >> 4, lc = tid & 15;   // loader: row 0..15, float4 col 0..15

    // Prefetch batch 0 into registers
    F4U kreg, vreg; float mreg;
    {
        const int s = s0 + lr;
        const int base = ((n * SK + s) * 8 + h) * DD;
        kreg.f = *((const float4*)(Kg + base) + lc);
        vreg.f = *((const float4*)(Vg + base) + lc);
        mreg = maskg[n * SK + s];
    }

    #pragma unroll 1
    for (int b = 0; b < S1_ROWS / 16; b++) {
        if (b) __syncthreads();   // prior compute done before overwriting tiles
        // Store current regs (phi+mask applied to K)
        F4U kw = kreg;
        kw.s[0] = phi(kw.s[0]) * mreg; kw.s[1] = phi(kw.s[1]) * mreg;
        kw.s[2] = phi(kw.s[2]) * mreg; kw.s[3] = phi(kw.s[3]) * mreg;
        ((float4*)&ks[lr][0])[lc] = kw.f;
        ((float4*)&vs[lr][0])[lc] = vreg.f;
        __syncthreads();
        // Prefetch next batch while computing
        if (b + 1 < S1_ROWS / 16) {
            const int s = s0 + (b + 1) * 16 + lr;
            const int base = ((n * SK + s) * 8 + h) * DD;
            kreg.f = *((const float4*)(Kg + base) + lc);
            vreg.f = *((const float4*)(Vg + base) + lc);
            mreg = maskg[n * SK + s];
        }
        #pragma unroll
        for (int r = 0; r < 16; r++) {
            F4U k4, v4;
            k4.f = ((const float4*)&ks[r][0])[td];
            v4.f = ((const float4*)&vs[r][0])[tm];
            #pragma unroll
            for (int i = 0; i < 4; i++) {
                const ull kd = pack2(k4.s[i], k4.s[i]);
                ffma2(acc[i][0], kd, v4.u[0]);
                ffma2(acc[i][1], kd, v4.u[1]);
            }
            if (tm == 0) {
                #pragma unroll
                for (int i = 0; i < 4; i++) ksum[i] += k4.s[i];
            }
        }
    }

    float* dst = g_KVp + ((sc * NH_TOT + nh) * DD + 4 * td) * MM + 4 * tm;
    #pragma unroll
    for (int i = 0; i < 4; i++) {
        F4U o; o.u[0] = acc[i][0]; o.u[1] = acc[i][1];
        *(float4*)(dst + i * MM) = o.f;
    }
    if (tm == 0) {
        float* kd = g_Ksp + (sc * NH_TOT + nh) * DD + 4 * td;
        #pragma unroll
        for (int i = 0; i < 4; i++) kd[i] = ksum[i];
    }
}

// ───────────────────────── Reduce partials ─────────────────────────
__global__ __launch_bounds__(256) void reduce_kernel() {
    const int idx = blockIdx.x * 256 + threadIdx.x;
    const int KV4 = NH_TOT * DD * MM / 4;    // 65536
    const int KS4 = NH_TOT * DD / 4;         // 1024
    if (idx < KV4) {
        float4 s = make_float4(0.f, 0.f, 0.f, 0.f);
        #pragma unroll 8
        for (int c = 0; c < S1_CHUNKS; c++) {
            float4 p = ((const float4*)g_KVp)[c * KV4 + idx];
            s.x += p.x; s.y += p.y; s.z += p.z; s.w += p.w;
        }
        ((float4*)g_KV)[idx] = s;
    } else if (idx < KV4 + KS4) {
        const int j = idx - KV4;
        float4 s = make_float4(0.f, 0.f, 0.f, 0.f);
        #pragma unroll 8
        for (int c = 0; c < S1_CHUNKS; c++) {
            float4 p = ((const float4*)g_Ksp)[c * KS4 + j];
            s.x += p.x; s.y += p.y; s.z += p.z; s.w += p.w;
        }
        ((float4*)g_Ksum)[j] = s;
    }
}

// ───────────────────────── Stage 2 ─────────────────────────
// grid (64 l-tiles, 64 nh), 256 threads, per-thread tile 4l x 4m.
// Q kept ROW-major in smem [l][d] (stride 68) -> contiguous float4 STS,
// no transpose scatter. Inner loop walks d in blocks of 4.
__global__ __launch_bounds__(256, 3) void stage2_kernel(
    const float* __restrict__ Qg, float* __restrict__ Outg)
{
    const int nh = blockIdx.y;
    const int n = nh >> 3, h = nh & 7;
    const int l0 = blockIdx.x * LTILE;
    const int tid = threadIdx.x;
    const int tl = tid >> 4;      // l tile: 4*tl..+3
    const int tm = tid & 15;      // m tile: 4*tm..+3

    __shared__ __align__(16) float Qs[LTILE][68];   // [l][d] row-major, padded
    __shared__ __align__(16) float KVs[DD][MM];
    __shared__ float ksums[DD];
    __shared__ float zs[LTILE];

    // Load Q tile with phi applied: float4 LDG + float4 STS (no transpose)
    #pragma unroll
    for (int u = 0; u < 4; u++) {
        const int i4 = tid + 256 * u;        // 0..1023 float4s
        const int l = i4 >> 4, c = i4 & 15;  // row l, float4 col c
        F4U q4; q4.f = *((const float4*)(Qg + ((n * LQ + l0 + l) * 8 + h) * DD) + c);
        q4.s[0] = phi(q4.s[0]); q4.s[1] = phi(q4.s[1]);
        q4.s[2] = phi(q4.s[2]); q4.s[3] = phi(q4.s[3]);
        *(float4*)&Qs[l][4 * c] = q4.f;
    }
    // Load KV (L2-resident) and Ksum
    #pragma unroll
    for (int u = 0; u < 4; u++)
        ((float4*)KVs)[tid + 256 * u] = ((const float4*)(g_KV + nh * DD * MM))[tid + 256 * u];
    if (tid < DD) ksums[tid] = g_Ksum[nh * DD + tid];
    __syncthreads();

    // z[l] = 1/(phi(q)[l] . Ksum + eps)   (contiguous float4 row reads)
    if (tid < LTILE) {
        float a = 0.f;
        #pragma unroll
        for (int c = 0; c < 16; c++) {
            F4U q4; q4.f = *(const float4*)&Qs[tid][4 * c];
            F4U s4; s4.f = *(const float4*)&ksums[4 * c];
            a = fmaf(q4.s[0], s4.s[0], a); a = fmaf(q4.s[1], s4.s[1], a);
            a = fmaf(q4.s[2], s4.s[2], a); a = fmaf(q4.s[3], s4.s[3], a);
        }
        zs[tid] = 1.f / (a + 1e-6f);
    }
    __syncthreads();

    ull acc[4][2];
    #pragma unroll
    for (int i = 0; i < 4; i++) { acc[i][0] = 0ull; acc[i][1] = 0ull; }

    #pragma unroll 4
    for (int d0 = 0; d0 < DD; d0 += 4) {
        F4U q4[4], k4[4];
        #pragma unroll
        for (int i = 0; i < 4; i++)
            q4[i].f = *(const float4*)&Qs[4 * tl + i][d0];         // broadcast
        #pragma unroll
        for (int j = 0; j < 4; j++)
            k4[j].f = ((const float4*)&KVs[d0 + j][0])[tm];
        #pragma unroll
        for (int j = 0; j < 4; j++) {
            #pragma unroll
            for (int i = 0; i < 4; i++) {
                const ull qq = pack2(q4[i].s[j], q4[i].s[j]);
                ffma2(acc[i][0], qq, k4[j].u[0]);
                ffma2(acc[i][1], qq, k4[j].u[1]);
            }
        }
    }

    #pragma unroll
    for (int i = 0; i < 4; i++) {
        const int l = l0 + 4 * tl + i;
        const float z = zs[4 * tl + i];
        const ull zz = pack2(z, z);
        F4U o;
        o.u[0] = mul2(acc[i][0], zz);
        o.u[1] = mul2(acc[i][1], zz);
        *(float4*)(Outg + ((n * LQ + l) * 8 + h) * MM + 4 * tm) = o.f;
    }
}

extern "C" void kernel_launch(void* const* d_in, const int* in_sizes, int n_in,
                              void* d_out, int out_size)
{
    const float* Q    = (const float*)d_in[0];
    const float* K    = (const float*)d_in[1];
    const float* V    = (const float*)d_in[2];
    const float* mask = (const float*)d_in[3];
    float* Out = (float*)d_out;

    stage1_kernel<<<dim3(NH_TOT, S1_CHUNKS), 256>>>(K, V, mask);
    reduce_kernel<<<260, 256>>>();
    stage2_kernel<<<dim3(LQ / LTILE, NH_TOT), 256>>>(Q, Out);
}